// round 1
// baseline (speedup 1.0000x reference)
#include <cuda_runtime.h>
#include <math.h>

#define BB 512
#define MM 4096
#define DD 64
#define CC 256
#define NT 512
#define RPT (MM / NT)   // 8 rows per thread
#define EPSF 1e-8f

__device__ __forceinline__ float blockReduceSum(float v, float* sh) {
    int lane = threadIdx.x & 31, wid = threadIdx.x >> 5;
    #pragma unroll
    for (int o = 16; o; o >>= 1) v += __shfl_xor_sync(0xffffffffu, v, o);
    __syncthreads();                 // protect sh from previous use
    if (lane == 0) sh[wid] = v;
    __syncthreads();
    if (wid == 0) {
        float x = (lane < (NT / 32)) ? sh[lane] : 0.0f;
        #pragma unroll
        for (int o = 8; o; o >>= 1) x += __shfl_xor_sync(0xffffffffu, x, o);
        if (lane == 0) sh[0] = x;
    }
    __syncthreads();
    return sh[0];
}

__device__ __forceinline__ float blockReduceMax(float v, float* sh) {
    int lane = threadIdx.x & 31, wid = threadIdx.x >> 5;
    #pragma unroll
    for (int o = 16; o; o >>= 1) v = fmaxf(v, __shfl_xor_sync(0xffffffffu, v, o));
    __syncthreads();
    if (lane == 0) sh[wid] = v;
    __syncthreads();
    if (wid == 0) {
        float x = (lane < (NT / 32)) ? sh[lane] : -INFINITY;
        #pragma unroll
        for (int o = 8; o; o >>= 1) x = fmaxf(x, __shfl_xor_sync(0xffffffffu, x, o));
        if (lane == 0) sh[0] = x;
    }
    __syncthreads();
    return sh[0];
}

__global__ __launch_bounds__(NT)
void ntm_head_kernel(
    const float* __restrict__ memory,     // (B, M, D)
    const float* __restrict__ cstate,     // (B, C)
    const float* __restrict__ prevw,      // (B, M)
    const float* __restrict__ Wk,         // (C, D)
    const float* __restrict__ Wb,         // (C, 1)
    const float* __restrict__ bb,         // (1,)
    const float* __restrict__ Wgate,      // (C, 1)
    const float* __restrict__ bgate,      // (1,)
    const float* __restrict__ Ws,         // (C, 3)
    const float* __restrict__ bs,         // (3,)
    const float* __restrict__ Wg,         // (C, 1)
    const float* __restrict__ bg,         // (1,)
    float* __restrict__ out)              // (B, M)
{
    __shared__ float sh_cs[CC];
    __shared__ float sh_qn[DD];
    __shared__ float sh_g[MM];
    __shared__ float sh_red[NT / 32];
    __shared__ float sh_scal[6];   // raw dots: 0 beta, 1 gate, 2 gamma, 3..5 shift
    __shared__ float sh_beta, sh_gate, sh_gamma, sh_s0, sh_s1, sh_s2;

    const int b    = blockIdx.x;
    const int tid  = threadIdx.x;
    const int lane = tid & 31;
    const int wid  = tid >> 5;

    // ---- load controller state row ----
    if (tid < CC) sh_cs[tid] = cstate[(size_t)b * CC + tid];
    __syncthreads();

    // ---- query = cs @ Wk  (threads 0..63, coalesced over d) ----
    if (tid < DD) {
        float acc = 0.0f;
        #pragma unroll 8
        for (int c = 0; c < CC; c++) acc = fmaf(sh_cs[c], Wk[c * DD + tid], acc);
        sh_qn[tid] = acc;   // raw query for now
    }
    // ---- six scalar projections, one warp each (warps 2..7) ----
    if (wid >= 2 && wid < 8) {
        int s = wid - 2;
        float acc = 0.0f;
        if (s < 3) {
            const float* W = (s == 0) ? Wb : (s == 1) ? Wgate : Wg;
            for (int c = lane; c < CC; c += 32) acc = fmaf(sh_cs[c], W[c], acc);
        } else {
            int col = s - 3;
            for (int c = lane; c < CC; c += 32) acc = fmaf(sh_cs[c], Ws[c * 3 + col], acc);
        }
        #pragma unroll
        for (int o = 16; o; o >>= 1) acc += __shfl_xor_sync(0xffffffffu, acc, o);
        if (lane == 0) sh_scal[s] = acc;
    }
    __syncthreads();

    // ---- normalize query (warp 0) ----
    if (wid == 0) {
        float a = sh_qn[lane], c = sh_qn[lane + 32];
        float v = a * a + c * c;
        #pragma unroll
        for (int o = 16; o; o >>= 1) v += __shfl_xor_sync(0xffffffffu, v, o);
        float inv = 1.0f / (sqrtf(v) + EPSF);
        sh_qn[lane]      = a * inv;
        sh_qn[lane + 32] = c * inv;
    }
    // ---- activations on the scalars (thread of warp 1) ----
    if (tid == 32) {
        sh_beta  = log1pf(__expf(sh_scal[0] + bb[0])) + 1.0f;
        sh_gate  = 1.0f / (1.0f + __expf(-(sh_scal[1] + bgate[0])));
        sh_gamma = log1pf(__expf(sh_scal[2] + bg[0])) + 1.0f;
        float a0 = sh_scal[3] + bs[0];
        float a1 = sh_scal[4] + bs[1];
        float a2 = sh_scal[5] + bs[2];
        float mx = fmaxf(a0, fmaxf(a1, a2));
        float e0 = __expf(a0 - mx), e1 = __expf(a1 - mx), e2 = __expf(a2 - mx);
        float inv = 1.0f / (e0 + e1 + e2);
        sh_s0 = e0 * inv; sh_s1 = e1 * inv; sh_s2 = e2 * inv;
    }
    __syncthreads();

    // ---- main streaming pass: cosine similarity over M rows ----
    float sim[RPT];
    const float4* qn4 = reinterpret_cast<const float4*>(sh_qn);
    float4 q[DD / 4];
    #pragma unroll
    for (int i = 0; i < DD / 4; i++) q[i] = qn4[i];

    const float4* mem4 = reinterpret_cast<const float4*>(
        memory + ((size_t)b * MM) * DD);
    #pragma unroll
    for (int k = 0; k < RPT; k++) {
        int m = tid + k * NT;
        const float4* row = mem4 + (size_t)m * (DD / 4);
        float dot = 0.0f, ss = 0.0f;
        #pragma unroll
        for (int i = 0; i < DD / 4; i++) {
            float4 v = row[i];
            dot = fmaf(v.x, q[i].x, dot); dot = fmaf(v.y, q[i].y, dot);
            dot = fmaf(v.z, q[i].z, dot); dot = fmaf(v.w, q[i].w, dot);
            ss  = fmaf(v.x, v.x, ss);     ss  = fmaf(v.y, v.y, ss);
            ss  = fmaf(v.z, v.z, ss);     ss  = fmaf(v.w, v.w, ss);
        }
        sim[k] = dot / (sqrtf(ss) + EPSF);
    }

    // ---- softmax(beta * sim) over M ----
    float beta = sh_beta;
    float lmax = -INFINITY;
    #pragma unroll
    for (int k = 0; k < RPT; k++) lmax = fmaxf(lmax, sim[k]);
    float smax = blockReduceMax(lmax, sh_red) * beta;

    float e[RPT];
    float lsum = 0.0f;
    #pragma unroll
    for (int k = 0; k < RPT; k++) {
        e[k] = __expf(beta * sim[k] - smax);
        lsum += e[k];
    }
    float ssum = blockReduceSum(lsum, sh_red);
    float invsum = 1.0f / ssum;

    // ---- gate interpolation, stash gated weights in SMEM ----
    float gate = sh_gate, gate1 = 1.0f - gate;
    const float* pw = prevw + (size_t)b * MM;
    #pragma unroll
    for (int k = 0; k < RPT; k++) {
        int m = tid + k * NT;
        sh_g[m] = fmaf(gate, e[k] * invsum, gate1 * pw[m]);
    }
    __syncthreads();

    // ---- circular 3-tap shift + sharpening ----
    float gamma = sh_gamma, s0 = sh_s0, s1 = sh_s1, s2 = sh_s2;
    float p[RPT];
    float psum = 0.0f;
    #pragma unroll
    for (int k = 0; k < RPT; k++) {
        int m  = tid + k * NT;
        int ml = (m == 0)      ? MM - 1 : m - 1;
        int mr = (m == MM - 1) ? 0      : m + 1;
        float sv = sh_g[ml] * s0 + sh_g[m] * s1 + sh_g[mr] * s2;
        p[k] = __powf(sv + EPSF, gamma);
        psum += p[k];
    }
    psum = blockReduceSum(psum, sh_red);
    float invp = 1.0f / (psum + EPSF);

    float* ob = out + (size_t)b * MM;
    #pragma unroll
    for (int k = 0; k < RPT; k++) ob[tid + k * NT] = p[k] * invp;
}

extern "C" void kernel_launch(void* const* d_in, const int* in_sizes, int n_in,
                              void* d_out, int out_size) {
    const float* memory = (const float*)d_in[0];
    const float* cstate = (const float*)d_in[1];
    const float* prevw  = (const float*)d_in[2];
    const float* Wk     = (const float*)d_in[3];
    const float* Wb     = (const float*)d_in[4];
    const float* bb     = (const float*)d_in[5];
    const float* Wgate  = (const float*)d_in[6];
    const float* bgate  = (const float*)d_in[7];
    const float* Ws     = (const float*)d_in[8];
    const float* bs     = (const float*)d_in[9];
    const float* Wg     = (const float*)d_in[10];
    const float* bg     = (const float*)d_in[11];
    float* out = (float*)d_out;

    ntm_head_kernel<<<BB, NT>>>(memory, cstate, prevw,
                                Wk, Wb, bb, Wgate, bgate, Ws, bs, Wg, bg, out);
}